// round 1
// baseline (speedup 1.0000x reference)
#include <cuda_runtime.h>
#include <cstdint>

#define DMODEL 256
#define D4     64          // DMODEL / 4 (float4 per row)
#define MAXN   100000

// ---------------- scratch (static device globals; no allocs allowed) --------
__device__ float g_h0[(size_t)MAXN * 256];   // post-aggregation features
__device__ float g_h1[(size_t)MAXN * 512];   // hidden layer
__device__ float g_colsum[256];
__device__ float g_colsq[256];
__device__ float g_scale[256];
__device__ float g_shift[256];
__device__ int   g_idx64;

// ---------------- helpers ----------------------------------------------------
__device__ __forceinline__ uint32_t f2tf(float f) {
    uint32_t r;
    asm("cvt.rna.tf32.f32 %0, %1;" : "=r"(r) : "f"(f));
    return r;
}

__device__ __forceinline__ void red4(float* p, float4 v) {
    asm volatile("red.global.add.v4.f32 [%0], {%1,%2,%3,%4};"
                 :: "l"(p), "f"(v.x), "f"(v.y), "f"(v.z), "f"(v.w) : "memory");
}

__device__ __forceinline__ void mma_tf32(float* c, const uint32_t* a, const uint32_t* b) {
    asm volatile(
        "mma.sync.aligned.m16n8k8.row.col.f32.tf32.tf32.f32 "
        "{%0,%1,%2,%3}, {%4,%5,%6,%7}, {%8,%9}, {%0,%1,%2,%3};"
        : "+f"(c[0]), "+f"(c[1]), "+f"(c[2]), "+f"(c[3])
        : "r"(a[0]), "r"(a[1]), "r"(a[2]), "r"(a[3]), "r"(b[0]), "r"(b[1]));
}

// ---------------- prolog: zero BN accumulators + sniff index dtype -----------
__global__ void k_prolog(const void* __restrict__ idxbuf) {
    int t = threadIdx.x;
    if (t < 256) { g_colsum[t] = 0.f; g_colsq[t] = 0.f; }
    if (t == 0) {
        // int64 indices < 2^32 -> every high 32-bit word is 0.
        // int32 indices -> high word is a random index in [0,N): ~never all zero.
        const unsigned long long* p = (const unsigned long long*)idxbuf;
        int is64 = 1;
        #pragma unroll 1
        for (int i = 0; i < 64; i++) {
            if ((p[i] >> 32) != 0ull) { is64 = 0; break; }
        }
        g_idx64 = is64;
    }
}

// ---------------- h0 = (1 + eps) * x ----------------------------------------
__global__ void k_init(const float4* __restrict__ x, const float* __restrict__ eps, int n4) {
    float s = 1.0f + __ldg(eps);
    float4* h0 = (float4*)g_h0;
    for (int i = blockIdx.x * blockDim.x + threadIdx.x; i < n4; i += gridDim.x * blockDim.x) {
        float4 v = x[i];
        v.x *= s; v.y *= s; v.z *= s; v.w *= s;
        h0[i] = v;
    }
}

// ---------------- h0 += scatter-sum over edges (one warp per edge) ----------
__global__ void k_scatter(const float* __restrict__ x,
                          const void* __restrict__ srcb,
                          const void* __restrict__ dstb, int E) {
    int w    = (int)((blockIdx.x * blockDim.x + threadIdx.x) >> 5);
    int lane = threadIdx.x & 31;
    if (w >= E) return;
    long long s, d;
    if (g_idx64) {
        s = ((const long long*)srcb)[w];
        d = ((const long long*)dstb)[w];
    } else {
        s = ((const int*)srcb)[w];
        d = ((const int*)dstb)[w];
    }
    const float4* xs = (const float4*)x + (size_t)s * D4;
    float4*       hd = (float4*)g_h0   + (size_t)d * D4;
    #pragma unroll
    for (int i = 0; i < 2; i++) {
        int c = lane + i * 32;
        float4 v = __ldg(xs + c);
        red4((float*)(hd + c), v);
    }
}

// ---------------- tf32 tensor-core GEMM:  C[M,NT] = A[M,K] @ B[K,NT] + bias --
// Block tile 128x64, BK=32, 8 warps (4x2), warp tile 32x32 of m16n8k8 frags.
template <int K, int NT, bool RELU, bool STATS>
__global__ __launch_bounds__(256, 2)
void k_gemm(const float* __restrict__ A, const float* __restrict__ B,
            const float* __restrict__ bias, float* __restrict__ C, int M) {
    __shared__ uint32_t As[128 * 36];   // stride 36 -> (4*gid + tig) conflict-free
    __shared__ uint32_t Bs[32 * 72];    // stride 72 -> (8*tig + gid) conflict-free
    __shared__ float s_sum[64];
    __shared__ float s_sq[64];

    const int tid  = threadIdx.x;
    const int warp = tid >> 5, lane = tid & 31;
    const int wm = warp >> 1, wn = warp & 1;          // 4x2 warp grid
    const int gid = lane >> 2, tig = lane & 3;
    const int bm = blockIdx.y, bn = blockIdx.x;
    const int row0 = bm * 128;

    float acc[2][4][4];
    #pragma unroll
    for (int i = 0; i < 2; i++)
        #pragma unroll
        for (int j = 0; j < 4; j++)
            #pragma unroll
            for (int l = 0; l < 4; l++) acc[i][j][l] = 0.f;

    const int KT = K / 32;
    for (int kt = 0; kt < KT; ++kt) {
        // load A tile: 128x32 floats = 1024 float4, 4 per thread
        #pragma unroll
        for (int j = 0; j < 4; j++) {
            int idx = tid + j * 256;
            int r = idx >> 3, c4 = idx & 7;
            int grow = row0 + r;
            float4 v = make_float4(0.f, 0.f, 0.f, 0.f);
            if (grow < M)
                v = *(const float4*)(A + (size_t)grow * K + kt * 32 + c4 * 4);
            uint4 t;
            t.x = f2tf(v.x); t.y = f2tf(v.y); t.z = f2tf(v.z); t.w = f2tf(v.w);
            *(uint4*)(&As[r * 36 + c4 * 4]) = t;
        }
        // load B tile: 32x64 floats = 512 float4, 2 per thread
        #pragma unroll
        for (int j = 0; j < 2; j++) {
            int idx = tid + j * 256;
            int r = idx >> 4, c4 = idx & 15;
            float4 v = *(const float4*)(B + (size_t)(kt * 32 + r) * NT + bn * 64 + c4 * 4);
            uint4 t;
            t.x = f2tf(v.x); t.y = f2tf(v.y); t.z = f2tf(v.z); t.w = f2tf(v.w);
            *(uint4*)(&Bs[r * 72 + c4 * 4]) = t;
        }
        __syncthreads();

        #pragma unroll
        for (int kk = 0; kk < 4; kk++) {
            uint32_t a[2][4], b[4][2];
            #pragma unroll
            for (int mf = 0; mf < 2; mf++) {
                int rb = wm * 32 + mf * 16 + gid;
                a[mf][0] = As[(rb    ) * 36 + kk * 8 + tig    ];
                a[mf][1] = As[(rb + 8) * 36 + kk * 8 + tig    ];
                a[mf][2] = As[(rb    ) * 36 + kk * 8 + tig + 4];
                a[mf][3] = As[(rb + 8) * 36 + kk * 8 + tig + 4];
            }
            #pragma unroll
            for (int nf = 0; nf < 4; nf++) {
                int col = wn * 32 + nf * 8 + gid;
                b[nf][0] = Bs[(kk * 8 + tig    ) * 72 + col];
                b[nf][1] = Bs[(kk * 8 + tig + 4) * 72 + col];
            }
            #pragma unroll
            for (int mf = 0; mf < 2; mf++)
                #pragma unroll
                for (int nf = 0; nf < 4; nf++)
                    mma_tf32(acc[mf][nf], a[mf], b[nf]);
        }
        __syncthreads();
    }

    // -------- epilogue: bias (+relu) (+BN stats) --------
    float lsum[8], lsq[8];
    #pragma unroll
    for (int i = 0; i < 8; i++) { lsum[i] = 0.f; lsq[i] = 0.f; }

    #pragma unroll
    for (int mf = 0; mf < 2; mf++) {
        #pragma unroll
        for (int h = 0; h < 2; h++) {
            int row = row0 + wm * 32 + mf * 16 + gid + h * 8;
            bool ok = row < M;
            #pragma unroll
            for (int nf = 0; nf < 4; nf++) {
                int col = bn * 64 + wn * 32 + nf * 8 + 2 * tig;
                float v0 = acc[mf][nf][2 * h + 0] + __ldg(&bias[col]);
                float v1 = acc[mf][nf][2 * h + 1] + __ldg(&bias[col + 1]);
                if (RELU) { v0 = fmaxf(v0, 0.f); v1 = fmaxf(v1, 0.f); }
                if (ok) {
                    *(float2*)(C + (size_t)row * NT + col) = make_float2(v0, v1);
                    if (STATS) {
                        lsum[nf * 2    ] += v0; lsq[nf * 2    ] += v0 * v0;
                        lsum[nf * 2 + 1] += v1; lsq[nf * 2 + 1] += v1 * v1;
                    }
                }
            }
        }
    }

    if (STATS) {
        if (tid < 64) { s_sum[tid] = 0.f; s_sq[tid] = 0.f; }
        __syncthreads();
        #pragma unroll
        for (int nf = 0; nf < 4; nf++)
            #pragma unroll
            for (int j = 0; j < 2; j++) {
                int lc = wn * 32 + nf * 8 + 2 * tig + j;
                atomicAdd(&s_sum[lc], lsum[nf * 2 + j]);
                atomicAdd(&s_sq[lc],  lsq[nf * 2 + j]);
            }
        __syncthreads();
        if (tid < 64) {
            atomicAdd(&g_colsum[bn * 64 + tid], s_sum[tid]);
            atomicAdd(&g_colsq[bn * 64 + tid],  s_sq[tid]);
        }
    }
}

// ---------------- BN finalize: per-column scale/shift ------------------------
__global__ void k_finalize(const float* __restrict__ gamma,
                           const float* __restrict__ beta, float invN) {
    int c = threadIdx.x;
    float mean = g_colsum[c] * invN;
    float var  = g_colsq[c] * invN - mean * mean;
    var = fmaxf(var, 0.f);
    float inv  = rsqrtf(var + 1e-5f);
    float sc   = gamma[c] * inv;
    g_scale[c] = sc;
    g_shift[c] = beta[c] - mean * sc;
}

// ---------------- BN apply (in place on d_out) -------------------------------
__global__ void k_bn(float4* __restrict__ out, int n4) {
    const float4* sc4 = (const float4*)g_scale;
    const float4* sh4 = (const float4*)g_shift;
    for (int i = blockIdx.x * blockDim.x + threadIdx.x; i < n4; i += gridDim.x * blockDim.x) {
        int c4 = i & (D4 - 1);
        float4 sc = sc4[c4], sh = sh4[c4];
        float4 v = out[i];
        v.x = fmaf(v.x, sc.x, sh.x);
        v.y = fmaf(v.y, sc.y, sh.y);
        v.z = fmaf(v.z, sc.z, sh.z);
        v.w = fmaf(v.w, sc.w, sh.w);
        out[i] = v;
    }
}

// ---------------- launch -----------------------------------------------------
extern "C" void kernel_launch(void* const* d_in, const int* in_sizes, int n_in,
                              void* d_out, int out_size) {
    const float* x     = (const float*)d_in[0];
    const void*  src   = d_in[1];
    const void*  dst   = d_in[2];
    const float* eps   = (const float*)d_in[3];
    const float* W1    = (const float*)d_in[4];
    const float* b1    = (const float*)d_in[5];
    const float* W2    = (const float*)d_in[6];
    const float* b2    = (const float*)d_in[7];
    const float* gamma = (const float*)d_in[8];
    const float* beta  = (const float*)d_in[9];
    float* out = (float*)d_out;

    int M  = in_sizes[0] / DMODEL;   // nodes
    int E  = in_sizes[1];            // edges
    int n4 = M * D4;

    void* ph0 = nullptr; cudaGetSymbolAddress(&ph0, g_h0);
    void* ph1 = nullptr; cudaGetSymbolAddress(&ph1, g_h1);

    k_prolog<<<1, 512>>>(src);
    k_init<<<1024, 256>>>((const float4*)x, eps, n4);

    int sblocks = (E + 7) / 8;                       // 8 warps/block, 1 edge/warp
    k_scatter<<<sblocks, 256>>>(x, src, dst, E);

    int mt = (M + 127) / 128;
    k_gemm<256, 512, true,  false><<<dim3(8, mt), 256>>>((const float*)ph0, W1, b1, (float*)ph1, M);
    k_gemm<512, 256, false, true ><<<dim3(4, mt), 256>>>((const float*)ph1, W2, b2, out, M);

    k_finalize<<<1, 256>>>(gamma, beta, 1.0f / (float)M);
    k_bn<<<2048, 256>>>((float4*)out, n4);
}